// round 1
// baseline (speedup 1.0000x reference)
#include <cuda_runtime.h>

#define N_NODES 100000
#define F 64
#define N_EDGES 500000
#define NCH 9
#define NEG 0.2f

typedef unsigned long long ull;

// ---------------- scratch (device globals; no allocations allowed) ----------
__device__ float g_h[(size_t)N_NODES * F];          // current layer h
__device__ float g_agg[(size_t)N_NODES * F];        // layer-1 raw weighted sum
__device__ float g_den[N_NODES];                    // layer-1 softmax denom
__device__ float g_ssrc[N_NODES];
__device__ float g_sdst[N_NODES];
__device__ float g_x2[(size_t)NCH * N_NODES * F];   // layer-2 raw sums (per ch)
__device__ float g_den2[(size_t)NCH * N_NODES];     // layer-2 denoms (per ch)

// ---------------- f32x2 helpers ----------------
__device__ __forceinline__ ull fma2(ull a, ull b, ull c) {
    ull d;
    asm("fma.rn.f32x2 %0, %1, %2, %3;" : "=l"(d) : "l"(a), "l"(b), "l"(c));
    return d;
}
__device__ __forceinline__ ull dup2(float x) {
    ull r;
    asm("mov.b64 %0, {%1, %1};" : "=l"(r) : "f"(x));
    return r;
}
__device__ __forceinline__ void unpack2(ull v, float& lo, float& hi) {
    asm("mov.b64 {%0, %1}, %2;" : "=f"(lo), "=f"(hi) : "l"(v));
}

// ---------------- GEMM + scores + self-loop init ----------------
// h = X @ W ; s_src = h@a_src ; s_dst = h@a_dst ;
// agg = exp(leaky(s_src+s_dst)) * h ; den = exp(leaky(s_src+s_dst))
// layer==1: X = relu(g_agg/g_den + b1) read on the fly.
__global__ __launch_bounds__(256) void gat_gemm(
    const float* __restrict__ Xemb,
    const float* __restrict__ Wall,
    const float* __restrict__ asall,
    const float* __restrict__ adall,
    const float* __restrict__ bprevall,
    int c, int layer)
{
    __shared__ __align__(16) float Wsh[F * F];
    __shared__ float2 xsh[16][F];
    __shared__ float ash[F], adsh[F], bsh[F];

    const float* W = Wall + (size_t)c * F * F;
    int tid = threadIdx.x;

    for (int i = tid; i < F * F / 4; i += 256)
        ((float4*)Wsh)[i] = ((const float4*)W)[i];
    if (tid < F) {
        ash[tid]  = asall[c * F + tid];
        adsh[tid] = adall[c * F + tid];
        bsh[tid]  = layer ? bprevall[c * F + tid] : 0.f;
    }
    __syncthreads();

    float* aggout;
    float* denout;
    if (layer == 0) { aggout = g_agg; denout = g_den; }
    else { aggout = g_x2 + (size_t)c * N_NODES * F; denout = g_den2 + (size_t)c * N_NODES; }

    const int tx = tid & 15;   // col group (4 cols)
    const int tp = tid >> 4;   // row pair (2 rows)
    const int ntiles = N_NODES / 32;

    for (int tile = blockIdx.x; tile < ntiles; tile += gridDim.x) {
        int rowbase = tile * 32;
        __syncthreads();
        // load 32 rows of X into xsh[pair][k] = (x[r0][k], x[r1][k])
        #pragma unroll
        for (int it = 0; it < 4; it++) {
            int idx = tid + 256 * it;
            int pr = idx >> 6;
            int k = idx & 63;
            int r0 = rowbase + 2 * pr, r1 = r0 + 1;
            float v0, v1;
            if (layer == 0) {
                v0 = Xemb[(size_t)r0 * F + k];
                v1 = Xemb[(size_t)r1 * F + k];
            } else {
                v0 = fmaxf(g_agg[(size_t)r0 * F + k] / g_den[r0] + bsh[k], 0.f);
                v1 = fmaxf(g_agg[(size_t)r1 * F + k] / g_den[r1] + bsh[k], 0.f);
            }
            xsh[pr][k] = make_float2(v0, v1);
        }
        __syncthreads();

        ull acc00 = 0, acc01 = 0, acc10 = 0, acc11 = 0;
        #pragma unroll
        for (int k = 0; k < F; k++) {
            ulonglong2 wv = *(const ulonglong2*)&Wsh[k * F + 4 * tx];
            float2 xv = xsh[tp][k];
            ull xd0 = dup2(xv.x), xd1 = dup2(xv.y);
            acc00 = fma2(wv.x, xd0, acc00);
            acc01 = fma2(wv.y, xd0, acc01);
            acc10 = fma2(wv.x, xd1, acc10);
            acc11 = fma2(wv.y, xd1, acc11);
        }
        float h00, h01, h02, h03, h10, h11, h12, h13;
        unpack2(acc00, h00, h01); unpack2(acc01, h02, h03);
        unpack2(acc10, h10, h11); unpack2(acc11, h12, h13);

        int r0 = rowbase + 2 * tp, r1 = r0 + 1;
        int cb = 4 * tx;
        float as0 = ash[cb], as1 = ash[cb + 1], as2 = ash[cb + 2], as3 = ash[cb + 3];
        float ad0 = adsh[cb], ad1 = adsh[cb + 1], ad2 = adsh[cb + 2], ad3 = adsh[cb + 3];

        float ps0 = h00 * as0 + h01 * as1 + h02 * as2 + h03 * as3;
        float pd0 = h00 * ad0 + h01 * ad1 + h02 * ad2 + h03 * ad3;
        float ps1 = h10 * as0 + h11 * as1 + h12 * as2 + h13 * as3;
        float pd1 = h10 * ad0 + h11 * ad1 + h12 * ad2 + h13 * ad3;
        #pragma unroll
        for (int off = 1; off < 16; off <<= 1) {
            ps0 += __shfl_xor_sync(0xffffffffu, ps0, off);
            pd0 += __shfl_xor_sync(0xffffffffu, pd0, off);
            ps1 += __shfl_xor_sync(0xffffffffu, ps1, off);
            pd1 += __shfl_xor_sync(0xffffffffu, pd1, off);
        }
        float e0 = ps0 + pd0; e0 = e0 > 0.f ? e0 : NEG * e0;
        float e1 = ps1 + pd1; e1 = e1 > 0.f ? e1 : NEG * e1;
        float w0 = __expf(e0);
        float w1 = __expf(e1);

        *(float4*)&g_h[(size_t)r0 * F + cb] = make_float4(h00, h01, h02, h03);
        *(float4*)&g_h[(size_t)r1 * F + cb] = make_float4(h10, h11, h12, h13);
        *(float4*)&aggout[(size_t)r0 * F + cb] = make_float4(w0 * h00, w0 * h01, w0 * h02, w0 * h03);
        *(float4*)&aggout[(size_t)r1 * F + cb] = make_float4(w1 * h10, w1 * h11, w1 * h12, w1 * h13);
        if (tx == 0) {
            g_ssrc[r0] = ps0; g_sdst[r0] = pd0; denout[r0] = w0;
            g_ssrc[r1] = ps1; g_sdst[r1] = pd1; denout[r1] = w1;
        }
    }
}

// ---------------- edge scatter: agg[dst] += w*h[src], den[dst] += w ---------
__global__ __launch_bounds__(256) void gat_edge(const int* __restrict__ EI, int c, int layer)
{
    const int* src = EI + (size_t)((c * 2 + layer) * 2) * N_EDGES;
    const int* dst = src + N_EDGES;
    float* agg;
    float* den;
    if (layer == 0) { agg = g_agg; den = g_den; }
    else { agg = g_x2 + (size_t)c * N_NODES * F; den = g_den2 + (size_t)c * N_NODES; }

    int tid = blockIdx.x * 256 + threadIdx.x;
    int e = tid >> 4;
    int j = tid & 15;
    if (e >= N_EDGES) return;

    int s = __ldg(&src[e]);
    int d = __ldg(&dst[e]);
    float ev = g_ssrc[s] + g_sdst[d];
    ev = ev > 0.f ? ev : NEG * ev;
    float w = __expf(ev);

    float4 hv = *(const float4*)&g_h[(size_t)s * F + 4 * j];
    float* p = &agg[(size_t)d * F + 4 * j];
    asm volatile("red.global.add.v4.f32 [%0], {%1,%2,%3,%4};"
                 :: "l"(p), "f"(w * hv.x), "f"(w * hv.y), "f"(w * hv.z), "f"(w * hv.w)
                 : "memory");
    if (j == 0) atomicAdd(&den[d], w);
}

// ---------------- channel attention combine ----------------
__global__ __launch_bounds__(256) void gat_final(
    const float* __restrict__ b2, const float* __restrict__ att, float* __restrict__ out)
{
    __shared__ float attsh[NCH * F];
    __shared__ float b2sh[NCH * F];
    for (int i = threadIdx.x; i < NCH * F; i += 256) { attsh[i] = att[i]; b2sh[i] = b2[i]; }
    __syncthreads();

    int tid = blockIdx.x * 256 + threadIdx.x;
    int node = tid >> 4;
    int j = tid & 15;
    if (node >= N_NODES) return;

    float4 xs[NCH];
    float sc[NCH];
    #pragma unroll
    for (int c = 0; c < NCH; c++) {
        float inv = 1.f / g_den2[(size_t)c * N_NODES + node];
        float4 v = *(const float4*)&g_x2[((size_t)c * N_NODES + node) * F + 4 * j];
        int cb = c * F + 4 * j;
        v.x = v.x * inv + b2sh[cb + 0];
        v.y = v.y * inv + b2sh[cb + 1];
        v.z = v.z * inv + b2sh[cb + 2];
        v.w = v.w * inv + b2sh[cb + 3];
        xs[c] = v;
        sc[c] = v.x * attsh[cb + 0] + v.y * attsh[cb + 1] + v.z * attsh[cb + 2] + v.w * attsh[cb + 3];
    }
    #pragma unroll
    for (int off = 1; off < 16; off <<= 1) {
        #pragma unroll
        for (int c = 0; c < NCH; c++) sc[c] += __shfl_xor_sync(0xffffffffu, sc[c], off);
    }
    float mx = sc[0];
    #pragma unroll
    for (int c = 1; c < NCH; c++) mx = fmaxf(mx, sc[c]);
    float sum = 0.f;
    float wch[NCH];
    #pragma unroll
    for (int c = 0; c < NCH; c++) { wch[c] = __expf(sc[c] - mx); sum += wch[c]; }
    float inv = 1.f / sum;
    float4 o = make_float4(0.f, 0.f, 0.f, 0.f);
    #pragma unroll
    for (int c = 0; c < NCH; c++) {
        float a = wch[c] * inv;
        o.x += a * xs[c].x; o.y += a * xs[c].y; o.z += a * xs[c].z; o.w += a * xs[c].w;
    }
    *(float4*)&out[(size_t)node * F + 4 * j] = o;
}

// ---------------- launch ----------------
extern "C" void kernel_launch(void* const* d_in, const int* in_sizes, int n_in,
                              void* d_out, int out_size)
{
    const float* emb = (const float*)d_in[0];
    const float* W1  = (const float*)d_in[1];
    const float* as1 = (const float*)d_in[2];
    const float* ad1 = (const float*)d_in[3];
    const float* b1  = (const float*)d_in[4];
    const float* W2  = (const float*)d_in[5];
    const float* as2 = (const float*)d_in[6];
    const float* ad2 = (const float*)d_in[7];
    const float* b2  = (const float*)d_in[8];
    const float* att = (const float*)d_in[9];
    const int*   EI  = (const int*)d_in[10];
    float* out = (float*)d_out;

    const int gemm_grid = 592;                       // 148 SMs * 4 blocks
    const int edge_grid = (N_EDGES * 16 + 255) / 256; // 31250
    const int fin_grid  = (N_NODES * 16 + 255) / 256; // 6250

    for (int c = 0; c < NCH; c++) {
        gat_gemm<<<gemm_grid, 256>>>(emb, W1, as1, ad1, b1, c, 0);
        gat_edge<<<edge_grid, 256>>>(EI, c, 0);
        gat_gemm<<<gemm_grid, 256>>>(emb, W2, as2, ad2, b1, c, 1);
        gat_edge<<<edge_grid, 256>>>(EI, c, 1);
    }
    gat_final<<<fin_grid, 256>>>(b2, att, out);
}